// round 3
// baseline (speedup 1.0000x reference)
#include <cuda_runtime.h>

// ValueRNN: GRU(T=512,B=256,I=64,H=512) + linear head (O=1).
//
// Decomposition: grid = 16 unit-slices x 8 batch-groups = 128 co-resident CTAs.
// Each CTA owns 32 hidden units x 32 batch rows. Per step it computes the 3-gate
// pre-activations for its tile (K-loop over 512 h + 64 x), applies the GRU
// update, writes its h slice to a global double buffer, accumulates its partial
// of the value head, and syncs its batch group via a monotonic counter barrier.
// Weights are pre-packed as float4 (wr,wz,wn,0) in [k][u] layout; X is
// pre-transposed to [t][i][b]. h traffic uses __ldcg/__stcg (L1 is not coherent
// across SMs within a launch).

#define T_STEPS   512
#define BATCH     256
#define IN_DIM    64
#define HID       512
#define K_TOT     576           // HID + IN_DIM
#define N_SLICES  16
#define N_BGROUPS 8
#define UNITS_PER_CTA 32        // HID / N_SLICES
#define BC        32            // BATCH / N_BGROUPS
#define THREADS   256

// Scratch (static device globals: allocation-free per harness rules)
__device__ float4   g_wpack[578 * HID];            // [k][u] -> (wr, wz, wn, 0); k=576 bias_hh, k=577 bias_ih
__device__ float    g_hbuf[2 * HID * BATCH];       // [buf][u][b]
__device__ float    g_XT[T_STEPS * IN_DIM * BATCH];// [t][i][b]
__device__ unsigned g_ctr[N_BGROUPS];              // per-batch-group barrier counters

// ---------------------------------------------------------------------------
// Pre-pass kernels
// ---------------------------------------------------------------------------

__global__ void init_kernel(float* __restrict__ out, const float* __restrict__ bias) {
    int i = blockIdx.x * blockDim.x + threadIdx.x;
    if (i < HID * BATCH) g_hbuf[i] = 0.0f;                 // h0 = 0 (buffer 0)
    if (i < T_STEPS * BATCH) out[i] = bias[0];             // V starts at scalar bias
    if (i < N_BGROUPS) g_ctr[i] = 0u;                      // reset barrier counters (each graph replay)
}

__global__ void pack_kernel(const float* __restrict__ wih, const float* __restrict__ whh,
                            const float* __restrict__ bih, const float* __restrict__ bhh) {
    int idx = blockIdx.x * blockDim.x + threadIdx.x;       // idx = k*HID + u
    if (idx >= 578 * HID) return;
    int k = idx / HID;
    int u = idx - k * HID;
    float4 v;
    if (k < HID) {                                         // recurrent weights, column k
        v.x = whh[(0 * HID + u) * HID + k];                // reset
        v.y = whh[(1 * HID + u) * HID + k];                // update
        v.z = whh[(2 * HID + u) * HID + k];                // new
    } else if (k < K_TOT) {                                // input weights, column k-HID
        int i = k - HID;
        v.x = wih[(0 * HID + u) * IN_DIM + i];
        v.y = wih[(1 * HID + u) * IN_DIM + i];
        v.z = wih[(2 * HID + u) * IN_DIM + i];
    } else if (k == K_TOT) {                               // bias_hh trio
        v.x = bhh[u]; v.y = bhh[HID + u]; v.z = bhh[2 * HID + u];
    } else {                                               // bias_ih trio
        v.x = bih[u]; v.y = bih[HID + u]; v.z = bih[2 * HID + u];
    }
    v.w = 0.0f;
    g_wpack[idx] = v;
}

__global__ void xt_kernel(const float* __restrict__ X) {
    int idx = blockIdx.x * blockDim.x + threadIdx.x;       // idx = (t*IN_DIM + i)*BATCH + b
    if (idx >= T_STEPS * IN_DIM * BATCH) return;
    int b = idx & (BATCH - 1);
    int r = idx >> 8;                                      // BATCH = 256
    int i = r & (IN_DIM - 1);
    int t = r >> 6;                                        // IN_DIM = 64
    g_XT[idx] = X[(t * BATCH + b) * IN_DIM + i];
}

// ---------------------------------------------------------------------------
// Main recurrent kernel
// ---------------------------------------------------------------------------

__device__ __forceinline__ void fma3x4(float4& ar, float4& az, float4& an,
                                       const float4 w, const float4 h) {
    ar.x = fmaf(w.x, h.x, ar.x); ar.y = fmaf(w.x, h.y, ar.y);
    ar.z = fmaf(w.x, h.z, ar.z); ar.w = fmaf(w.x, h.w, ar.w);
    az.x = fmaf(w.y, h.x, az.x); az.y = fmaf(w.y, h.y, az.y);
    az.z = fmaf(w.y, h.z, az.z); az.w = fmaf(w.y, h.w, az.w);
    an.x = fmaf(w.z, h.x, an.x); an.y = fmaf(w.z, h.y, an.y);
    an.z = fmaf(w.z, h.z, an.z); an.w = fmaf(w.z, h.w, an.w);
}

__device__ __forceinline__ float sigmoidf_fast(float x) {
    return 1.0f / (1.0f + __expf(-x));
}

__global__ void __launch_bounds__(THREADS, 1)
gru_main(const float* __restrict__ vw, float* __restrict__ out) {
    __shared__ float svp[BC];

    const int slice = blockIdx.x;          // 0..15 (unit slice)
    const int bg    = blockIdx.y;          // 0..7  (batch group)
    const int tid   = threadIdx.x;
    const int u_local = tid >> 3;          // 0..31
    const int bsub    = tid & 7;           // 0..7
    const int u    = slice * UNITS_PER_CTA + u_local;
    const int b0   = bg * BC;
    const int bcol = b0 + bsub * 4;        // this thread's 4 batch columns

    const float vwu = __ldg(&vw[u]);
    if (tid < BC) svp[tid] = 0.0f;
    __syncthreads();

    const float4* __restrict__ wp4 = g_wpack;

    for (int t = 0; t < T_STEPS; ++t) {
        const int cur = t & 1;
        const int nxt = cur ^ 1;
        const float* hb = g_hbuf + cur * (HID * BATCH);

        float4 awr = make_float4(0.f, 0.f, 0.f, 0.f), awz = awr, awn = awr;
        // Recurrent part: K over hidden units (h from the other CTAs -> L2 only)
        #pragma unroll 8
        for (int k = 0; k < HID; ++k) {
            float4 w = __ldg(wp4 + (k * HID + u));
            float4 h = __ldcg((const float4*)(hb + k * BATCH + bcol));
            fma3x4(awr, awz, awn, w, h);
        }

        float4 axr = make_float4(0.f, 0.f, 0.f, 0.f), axz = axr, axn = axr;
        const float* xt = g_XT + t * (IN_DIM * BATCH);
        // Input part: K over input features (static, L1-cacheable)
        #pragma unroll 8
        for (int i = 0; i < IN_DIM; ++i) {
            float4 w = __ldg(wp4 + ((HID + i) * HID + u));
            float4 x = __ldg((const float4*)(xt + i * BATCH + bcol));
            fma3x4(axr, axz, axn, w, x);
        }

        // Biases: awr/z/n += bias_hh, axr/z/n += bias_ih (broadcast over batch)
        float4 bh = __ldg(wp4 + (576 * HID + u));
        float4 bi = __ldg(wp4 + (577 * HID + u));
        awr.x += bh.x; awr.y += bh.x; awr.z += bh.x; awr.w += bh.x;
        awz.x += bh.y; awz.y += bh.y; awz.z += bh.y; awz.w += bh.y;
        awn.x += bh.z; awn.y += bh.z; awn.z += bh.z; awn.w += bh.z;
        axr.x += bi.x; axr.y += bi.x; axr.z += bi.x; axr.w += bi.x;
        axz.x += bi.y; axz.y += bi.y; axz.z += bi.y; axz.w += bi.y;
        axn.x += bi.z; axn.y += bi.z; axn.z += bi.z; axn.w += bi.z;

        // GRU update for (u, bcol..bcol+3)
        float4 hold = __ldcg((const float4*)(hb + u * BATCH + bcol));
        float4 hn;
        {
            float r = sigmoidf_fast(axr.x + awr.x);
            float z = sigmoidf_fast(axz.x + awz.x);
            float n = tanhf(axn.x + r * awn.x);
            hn.x = n + z * (hold.x - n);
        }
        {
            float r = sigmoidf_fast(axr.y + awr.y);
            float z = sigmoidf_fast(axz.y + awz.y);
            float n = tanhf(axn.y + r * awn.y);
            hn.y = n + z * (hold.y - n);
        }
        {
            float r = sigmoidf_fast(axr.z + awr.z);
            float z = sigmoidf_fast(axz.z + awz.z);
            float n = tanhf(axn.z + r * awn.z);
            hn.z = n + z * (hold.z - n);
        }
        {
            float r = sigmoidf_fast(axr.w + awr.w);
            float z = sigmoidf_fast(axz.w + awz.w);
            float n = tanhf(axn.w + r * awn.w);
            hn.w = n + z * (hold.w - n);
        }

        float* hw = g_hbuf + nxt * (HID * BATCH) + u * BATCH + bcol;
        __stcg((float4*)hw, hn);

        // Value head partial: svp[b] += vw[u] * h_new[b][u]
        atomicAdd(&svp[bsub * 4 + 0], vwu * hn.x);
        atomicAdd(&svp[bsub * 4 + 1], vwu * hn.y);
        atomicAdd(&svp[bsub * 4 + 2], vwu * hn.z);
        atomicAdd(&svp[bsub * 4 + 3], vwu * hn.w);

        __syncthreads();
        if (tid < BC) {
            atomicAdd(&out[t * BATCH + b0 + tid], svp[tid]);
            svp[tid] = 0.0f;
        }

        // Inter-CTA barrier for this batch group:
        // every thread fences its h stores, then one thread arrives + spins.
        __threadfence();
        __syncthreads();
        if (tid == 0) {
            atomicAdd(&g_ctr[bg], 1u);
            volatile unsigned* c = &g_ctr[bg];
            const unsigned target = (unsigned)(N_SLICES * (t + 1));
            while (*c < target) { __nanosleep(32); }
        }
        __syncthreads();
        __threadfence();   // acquire side before reading peers' h next step
    }
}

// ---------------------------------------------------------------------------
// Launch
// ---------------------------------------------------------------------------

extern "C" void kernel_launch(void* const* d_in, const int* in_sizes, int n_in,
                              void* d_out, int out_size) {
    const float* X    = (const float*)d_in[0];   // (T, B, I)
    const float* wih  = (const float*)d_in[1];   // (3H, I)
    const float* whh  = (const float*)d_in[2];   // (3H, H)
    const float* bih  = (const float*)d_in[3];   // (3H,)
    const float* bhh  = (const float*)d_in[4];   // (3H,)
    const float* vw   = (const float*)d_in[5];   // (O=1, H)
    const float* bias = (const float*)d_in[6];   // (O=1,)
    float* out = (float*)d_out;                  // (T, B, 1)

    init_kernel<<<(T_STEPS * BATCH + 255) / 256, 256>>>(out, bias);
    pack_kernel<<<(578 * HID + 255) / 256, 256>>>(wih, whh, bih, bhh);
    xt_kernel<<<(T_STEPS * IN_DIM * BATCH + 255) / 256, 256>>>(X);

    dim3 grid(N_SLICES, N_BGROUPS, 1);
    gru_main<<<grid, THREADS>>>(vw, out);
}

// round 5
// speedup vs baseline: 1.3212x; 1.3212x over previous
#include <cuda_runtime.h>
#include <cstdint>

// ValueRNN: GRU(T=512,B=256,I=64,H=512) + linear head (O=1).
// Grid = 16 unit-slices x 8 batch-groups = 128 co-resident CTAs, 256 thr.
// Per step: 9 K-chunks of 64 (8 hidden + 1 input), double-buffered in smem.
// w layout per (k,slice) row (640 B): [u0..u31: (wr,wr,wz,wz) 16B] [u0..u31: wn 4B]
//   -> inner iter: ld.shared.v2.b64 (wrzz) + ld.shared.b32 (wn) + v2.b64 (h),
//      all 16/4-aligned, 3 smem wavefronts, 6x fma.rn.f32x2.
// w arrives via cp.async (prefetch distance 1); h via ldcg->STS register pipe.
// Inter-CTA sync: per-batch-group monotonic counter barrier in L2.

#define T_STEPS   512
#define BATCH     256
#define IN_DIM    64
#define HID       512
#define K_TOT     576
#define N_SLICES  16
#define N_BGROUPS 8
#define THREADS   256
#define CHUNK     64
#define NCHUNK    9            // 576 / 64

typedef unsigned long long u64;

#define WROW_F    160          // floats per (k, slice) row: 32*(4+1) = 640 B
__device__ __align__(256) float g_wpk[K_TOT * 16 * WROW_F];   // ~5.9 MB
__device__ __align__(16)  float g_hbuf[2 * HID * BATCH];      // [buf][u][b]
__device__ __align__(16)  float g_XT[T_STEPS * IN_DIM * BATCH]; // [t][i][b]
__device__ unsigned g_ctr[N_BGROUPS];

// dynamic smem layout (bytes):
//   wsm: 2 x (64 rows x 640B) = 81920
//   hsm: 2 x (64 rows x 128B) = 16384
#define WBUF_BYTES 40960
#define HSM_OFF    81920
#define HBUF_BYTES 8192
#define SMEM_BYTES (81920 + 16384)

// ---------------------------------------------------------------------------
// Pre-pass kernels
// ---------------------------------------------------------------------------

__global__ void init_kernel(float* __restrict__ out, const float* __restrict__ bias) {
    int i = blockIdx.x * blockDim.x + threadIdx.x;
    if (i < HID * BATCH) g_hbuf[i] = 0.0f;
    if (i < T_STEPS * BATCH) out[i] = bias[0];
    if (i < N_BGROUPS) g_ctr[i] = 0u;
}

__global__ void pack_kernel(const float* __restrict__ wih, const float* __restrict__ whh) {
    int idx = blockIdx.x * blockDim.x + threadIdx.x;    // idx = (k*512 + u)*3 + g
    if (idx >= K_TOT * 512 * 3) return;
    int g = idx % 3;
    int r = idx / 3;
    int u = r & 511;
    int k = r >> 9;
    float v;
    if (k < HID) v = whh[(g * HID + u) * HID + k];
    else         v = wih[(g * HID + u) * IN_DIM + (k - HID)];
    int slice = u >> 5, ul = u & 31;
    float* row = g_wpk + (k * 16 + slice) * WROW_F;
    if (g == 0)      { row[ul * 4 + 0] = v; row[ul * 4 + 1] = v; }
    else if (g == 1) { row[ul * 4 + 2] = v; row[ul * 4 + 3] = v; }
    else             { row[128 + ul] = v; }
}

__global__ void xt_kernel(const float* __restrict__ X) {
    int idx = blockIdx.x * blockDim.x + threadIdx.x;    // (t*64 + i)*256 + b
    if (idx >= T_STEPS * IN_DIM * BATCH) return;
    int b = idx & 255;
    int r = idx >> 8;
    int i = r & 63;
    int t = r >> 6;
    g_XT[idx] = X[(t * BATCH + b) * IN_DIM + i];
}

// ---------------------------------------------------------------------------
// PTX helpers
// ---------------------------------------------------------------------------

__device__ __forceinline__ uint32_t smem_u32(const void* p) {
    uint32_t a;
    asm("{ .reg .u64 t; cvta.to.shared.u64 t, %1; cvt.u32.u64 %0, t; }" : "=r"(a) : "l"(p));
    return a;
}
__device__ __forceinline__ u64 fma2(u64 a, u64 b, u64 c) {
    u64 d;
    asm("fma.rn.f32x2 %0, %1, %2, %3;" : "=l"(d) : "l"(a), "l"(b), "l"(c));
    return d;
}
__device__ __forceinline__ void lds_v2u64(u64& a, u64& b, uint32_t addr) {
    asm volatile("ld.shared.v2.b64 {%0,%1}, [%2];" : "=l"(a), "=l"(b) : "r"(addr));
}
__device__ __forceinline__ float lds_f32(uint32_t addr) {
    float a;
    asm volatile("ld.shared.b32 %0, [%1];" : "=f"(a) : "r"(addr));
    return a;
}
__device__ __forceinline__ u64 dup2(float w) {
    u64 d;
    asm("mov.b64 %0, {%1,%1};" : "=l"(d) : "f"(w));
    return d;
}
__device__ __forceinline__ float2 unpk(u64 v) {
    float2 r;
    asm("mov.b64 {%0,%1}, %2;" : "=f"(r.x), "=f"(r.y) : "l"(v));
    return r;
}
__device__ __forceinline__ void cp16(uint32_t dst, const void* src) {
    asm volatile("cp.async.cg.shared.global [%0], [%1], 16;" :: "r"(dst), "l"(src));
}
#define CP_COMMIT() asm volatile("cp.async.commit_group;" ::: "memory")
#define CP_WAIT0()  asm volatile("cp.async.wait_group 0;" ::: "memory")

__device__ __forceinline__ float sigf(float x) { return 1.0f / (1.0f + __expf(-x)); }
__device__ __forceinline__ float tanhf_fast(float x) {
    return 2.0f / (1.0f + __expf(-2.0f * x)) - 1.0f;
}

// ---------------------------------------------------------------------------
// Main recurrent kernel
// ---------------------------------------------------------------------------

__global__ void __launch_bounds__(THREADS, 1)
gru_main(const float* __restrict__ vw,
         const float* __restrict__ bih, const float* __restrict__ bhh,
         float* __restrict__ out) {
    extern __shared__ char smem[];
    __shared__ float svp[32];

    const uint32_t sbase = smem_u32(smem);
    const int slice = blockIdx.x;            // 0..15
    const int bg    = blockIdx.y;            // 0..7
    const int tid   = threadIdx.x;
    const int u_local = tid >> 3;            // 0..31
    const int bsub    = tid & 7;             // 0..7
    const int u_g  = slice * 32 + u_local;
    const int b0   = bg * 32;
    const int bcolg = b0 + bsub * 4;

    // staging mapping: row sr = tid>>2 (0..63), quarter sq = tid&3
    const int sr = tid >> 2;
    const int sq = tid & 3;

    const float vwu = __ldg(&vw[u_g]);
    const float bir = __ldg(&bih[u_g]),         bhr = __ldg(&bhh[u_g]);
    const float biz = __ldg(&bih[HID + u_g]),   bhz = __ldg(&bhh[HID + u_g]);
    const float bin = __ldg(&bih[2*HID + u_g]), bhn = __ldg(&bhh[2*HID + u_g]);

    // per-thread smem byte offsets within a buffer
    const uint32_t wrz_off = (uint32_t)(u_local * 16);        // (wr,wr,wz,wz)
    const uint32_t wn_off  = (uint32_t)(512 + u_local * 4);   // wn scalar
    const uint32_t h_off   = (uint32_t)(HSM_OFF + bsub * 16);

    // cp.async: per chunk each thread copies 160 B (10 x 16B)
    //   src row (k,slice): g_wpk + ((k*16+slice)*WROW_F), 640 B
    const float* wsrc0 = g_wpk + slice * WROW_F;              // + k*(16*WROW_F)
    const uint32_t wdst_thr = (uint32_t)(sr * 640 + sq * 160);

    if (tid < 32) svp[tid] = 0.0f;
    __syncthreads();

    float4 ha, hb4;   // h staging register pipeline (8 floats)

    #pragma unroll 1
    for (int t = 0; t < T_STEPS; ++t) {
        const int cur = t & 1;
        const float* hb = g_hbuf + cur * (HID * BATCH);
        const float* xt = g_XT + t * (IN_DIM * BATCH);

        // prefetch h_old for the epilogue
        float4 hold = __ldcg((const float4*)(hb + u_g * BATCH + bcolg));

        #define SRC(c) (((c) < 8) ? (hb + (c) * (CHUNK * BATCH)) : xt)

        // ---- prologue: fill pipe ----
        {
            const float* s0 = SRC(0) + sr * BATCH + b0 + sq * 8;
            ha  = __ldcg((const float4*)s0);
            hb4 = __ldcg((const float4*)(s0 + 4));
        }
        {   // cp.async w chunk 0 -> wbuf 0
            const char* ws = (const char*)(wsrc0 + (size_t)sr * (16 * WROW_F)) + sq * 160;
            uint32_t dst = sbase + wdst_thr;
            #pragma unroll
            for (int j = 0; j < 10; ++j) cp16(dst + j * 16, ws + j * 16);
            CP_COMMIT();
        }
        {   // stage h chunk 0 -> hbuf 0, then load regs for chunk 1
            float* hdst = (float*)(smem + HSM_OFF) + sr * 32 + sq * 8;
            *(float4*)hdst = ha;
            *(float4*)(hdst + 4) = hb4;
            const float* s1 = SRC(1) + sr * BATCH + b0 + sq * 8;
            ha  = __ldcg((const float4*)s1);
            hb4 = __ldcg((const float4*)(s1 + 4));
        }
        CP_WAIT0();
        __syncthreads();

        u64 ar0 = 0, ar1 = 0, az0 = 0, az1 = 0;
        u64 an0 = 0, an1 = 0;        // hidden-part n gate
        u64 ax0 = 0, ax1 = 0;        // input-part n gate

        // ---- chunk loop ----
        #pragma unroll 1
        for (int c = 0; c < NCHUNK; ++c) {
            if (c < NCHUNK - 1) {
                // stage h chunk c+1 (regs loaded one chunk ago)
                float* hdst = (float*)(smem + HSM_OFF + ((c + 1) & 1) * HBUF_BYTES)
                              + sr * 32 + sq * 8;
                *(float4*)hdst = ha;
                *(float4*)(hdst + 4) = hb4;
                if (c < NCHUNK - 2) {
                    const float* s = SRC(c + 2) + sr * BATCH + b0 + sq * 8;
                    ha  = __ldcg((const float4*)s);
                    hb4 = __ldcg((const float4*)(s + 4));
                }
                // cp.async w chunk c+1 -> other wbuf
                const char* ws = (const char*)(wsrc0
                                  + (size_t)((c + 1) * CHUNK + sr) * (16 * WROW_F))
                                  + sq * 160;
                uint32_t dst = sbase + ((c + 1) & 1) * WBUF_BYTES + wdst_thr;
                #pragma unroll
                for (int j = 0; j < 10; ++j) cp16(dst + j * 16, ws + j * 16);
            }
            CP_COMMIT();

            // compute chunk c (all operands in smem)
            const uint32_t wa  = sbase + (c & 1) * WBUF_BYTES + wrz_off;
            const uint32_t wna = sbase + (c & 1) * WBUF_BYTES + wn_off;
            const uint32_t hc  = sbase + h_off + (c & 1) * HBUF_BYTES;
            u64 n0 = 0, n1 = 0;
            #pragma unroll 8
            for (int k = 0; k < CHUNK; ++k) {
                u64 wrr, wzz, h01, h23;
                lds_v2u64(wrr, wzz, wa + (uint32_t)(k * 640));
                u64 wnn = dup2(lds_f32(wna + (uint32_t)(k * 640)));
                lds_v2u64(h01, h23, hc + (uint32_t)(k * 128));
                ar0 = fma2(wrr, h01, ar0); ar1 = fma2(wrr, h23, ar1);
                az0 = fma2(wzz, h01, az0); az1 = fma2(wzz, h23, az1);
                n0  = fma2(wnn, h01, n0);  n1  = fma2(wnn, h23, n1);
            }
            if (c < 8) {
                an0 = fma2(0x3f8000003f800000ull, n0, an0);
                an1 = fma2(0x3f8000003f800000ull, n1, an1);
            } else {
                ax0 = fma2(0x3f8000003f800000ull, n0, ax0);
                ax1 = fma2(0x3f8000003f800000ull, n1, ax1);
            }

            CP_WAIT0();
            __syncthreads();
        }

        // ---- epilogue: GRU update for (u_g, bcolg..bcolg+3) ----
        float2 arl = unpk(ar0), arh = unpk(ar1);
        float2 azl = unpk(az0), azh = unpk(az1);
        float2 anl = unpk(an0), anh2 = unpk(an1);
        float2 axl = unpk(ax0), axh = unpk(ax1);

        float4 hn;
        {
            float r = sigf(arl.x + bir + bhr);
            float z = sigf(azl.x + biz + bhz);
            float n = tanhf_fast(axl.x + bin + r * (anl.x + bhn));
            hn.x = n + z * (hold.x - n);
        }
        {
            float r = sigf(arl.y + bir + bhr);
            float z = sigf(azl.y + biz + bhz);
            float n = tanhf_fast(axl.y + bin + r * (anl.y + bhn));
            hn.y = n + z * (hold.y - n);
        }
        {
            float r = sigf(arh.x + bir + bhr);
            float z = sigf(azh.x + biz + bhz);
            float n = tanhf_fast(axh.x + bin + r * (anh2.x + bhn));
            hn.z = n + z * (hold.z - n);
        }
        {
            float r = sigf(arh.y + bir + bhr);
            float z = sigf(azh.y + biz + bhz);
            float n = tanhf_fast(axh.y + bin + r * (anh2.y + bhn));
            hn.w = n + z * (hold.w - n);
        }

        float* hw = g_hbuf + (cur ^ 1) * (HID * BATCH) + u_g * BATCH + bcolg;
        __stcg((float4*)hw, hn);

        // value head: reduce over the 4 u_locals per warp, then CTA, then global
        float c0 = vwu * hn.x, c1 = vwu * hn.y, c2 = vwu * hn.z, c3 = vwu * hn.w;
        c0 += __shfl_down_sync(0xffffffffu, c0, 16);
        c1 += __shfl_down_sync(0xffffffffu, c1, 16);
        c2 += __shfl_down_sync(0xffffffffu, c2, 16);
        c3 += __shfl_down_sync(0xffffffffu, c3, 16);
        c0 += __shfl_down_sync(0xffffffffu, c0, 8);
        c1 += __shfl_down_sync(0xffffffffu, c1, 8);
        c2 += __shfl_down_sync(0xffffffffu, c2, 8);
        c3 += __shfl_down_sync(0xffffffffu, c3, 8);
        if ((tid & 31) < 8) {
            atomicAdd(&svp[(tid & 7) * 4 + 0], c0);
            atomicAdd(&svp[(tid & 7) * 4 + 1], c1);
            atomicAdd(&svp[(tid & 7) * 4 + 2], c2);
            atomicAdd(&svp[(tid & 7) * 4 + 3], c3);
        }
        __syncthreads();
        if (tid < 32) {
            atomicAdd(&out[t * BATCH + b0 + tid], svp[tid]);
            svp[tid] = 0.0f;
        }

        // ---- inter-CTA barrier for this batch group ----
        __threadfence();
        __syncthreads();
        if (tid == 0) {
            atomicAdd(&g_ctr[bg], 1u);
            volatile unsigned* cc = &g_ctr[bg];
            const unsigned target = (unsigned)(N_SLICES * (t + 1));
            while (*cc < target) { __nanosleep(32); }
        }
        __syncthreads();
        __threadfence();
        #undef SRC
    }
}

// ---------------------------------------------------------------------------
// Launch
// ---------------------------------------------------------------------------

extern "C" void kernel_launch(void* const* d_in, const int* in_sizes, int n_in,
                              void* d_out, int out_size) {
    const float* X    = (const float*)d_in[0];   // (T, B, I)
    const float* wih  = (const float*)d_in[1];   // (3H, I)
    const float* whh  = (const float*)d_in[2];   // (3H, H)
    const float* bih  = (const float*)d_in[3];   // (3H,)
    const float* bhh  = (const float*)d_in[4];   // (3H,)
    const float* vw   = (const float*)d_in[5];   // (1, H)
    const float* bias = (const float*)d_in[6];   // (1,)
    float* out = (float*)d_out;                  // (T, B, 1)

    cudaFuncSetAttribute(gru_main, cudaFuncAttributeMaxDynamicSharedMemorySize,
                         SMEM_BYTES);

    init_kernel<<<(T_STEPS * BATCH + 255) / 256, 256>>>(out, bias);
    pack_kernel<<<(K_TOT * 512 * 3 + 255) / 256, 256>>>(wih, whh);
    xt_kernel<<<(T_STEPS * IN_DIM * BATCH + 255) / 256, 256>>>(X);

    dim3 grid(N_SLICES, N_BGROUPS, 1);
    gru_main<<<grid, THREADS, SMEM_BYTES>>>(vw, bih, bhh, out);
}